// round 8
// baseline (speedup 1.0000x reference)
#include <cuda_runtime.h>
#include <cstdint>

#define N_NODES 100000
#define N_EDGES 640000
#define HID     128

// ---------------- scratch (static device globals; no allocation) ----------------
__device__ float g_A[(size_t)N_NODES * HID];   // ping
__device__ float g_B[(size_t)N_NODES * HID];   // pong
__device__ float g_S[(size_t)N_NODES * HID];   // support = X @ W
__device__ int   g_cnt[N_NODES];
__device__ int   g_rowptr[N_NODES];
__device__ int   g_cursor[N_NODES];
__device__ int   g_csr_src[N_EDGES];
__device__ float g_csr_val[N_EDGES];
__device__ int   g_blocksums[128];
// W fragments in mma-fragment order: [chunk(16)][ntile(16)][lane(32)][j(2)]
__device__ uint32_t g_Bfh[16 * 16 * 32 * 2];   // tf32 hi
__device__ uint32_t g_Bfl[16 * 16 * 32 * 2];   // tf32 lo

__device__ __forceinline__ uint32_t tf32_rna(float x) {
    uint32_t r;
    asm("cvt.rna.tf32.f32 %0, %1;" : "=r"(r) : "f"(x));
    return r;
}

// D(16x8,f32) += A(16x8,tf32,row) * B(8x8,tf32,col)
#define MMA_TF32(d, a, bx, by) \
    asm volatile("mma.sync.aligned.m16n8k8.row.col.f32.tf32.tf32.f32 " \
                 "{%0,%1,%2,%3}, {%4,%5,%6,%7}, {%8,%9}, {%0,%1,%2,%3};" \
                 : "+f"((d)[0]), "+f"((d)[1]), "+f"((d)[2]), "+f"((d)[3]) \
                 : "r"((a)[0]), "r"((a)[1]), "r"((a)[2]), "r"((a)[3]), \
                   "r"(bx), "r"(by))

// ---------------- CSR build ----------------
__global__ void hist_kernel(const int* __restrict__ dst) {
    int e = blockIdx.x * blockDim.x + threadIdx.x;
    if (e < N_EDGES) atomicAdd(&g_cnt[dst[e]], 1);
}

__global__ void scan1_kernel() {
    __shared__ int sh[1024];
    int tid = threadIdx.x;
    int i = blockIdx.x * 1024 + tid;
    int v = (i < N_NODES) ? g_cnt[i] : 0;
    sh[tid] = v;
    __syncthreads();
    for (int off = 1; off < 1024; off <<= 1) {
        int t = (tid >= off) ? sh[tid - off] : 0;
        __syncthreads();
        sh[tid] += t;
        __syncthreads();
    }
    if (i < N_NODES) g_rowptr[i] = sh[tid] - v;   // exclusive
    if (tid == 1023) g_blocksums[blockIdx.x] = sh[1023];
}

__global__ void scan2_kernel(int nblocks) {
    if (threadIdx.x == 0) {
        int run = 0;
        for (int b = 0; b < nblocks; b++) {
            int t = g_blocksums[b];
            g_blocksums[b] = run;
            run += t;
        }
    }
}

__global__ void scan3_kernel() {
    int i = blockIdx.x * 1024 + threadIdx.x;
    if (i < N_NODES) {
        int r = g_rowptr[i] + g_blocksums[blockIdx.x];
        g_rowptr[i] = r;
        g_cursor[i] = r;
    }
}

__global__ void scatter_kernel(const int* __restrict__ src,
                               const int* __restrict__ dst,
                               const float* __restrict__ val) {
    int e = blockIdx.x * blockDim.x + threadIdx.x;
    if (e < N_EDGES) {
        int d = dst[e];
        int pos = atomicAdd(&g_cursor[d], 1);
        g_csr_src[pos] = src[e];
        g_csr_val[pos] = val[e];
    }
}

// ---------------- embedding concat ----------------
__global__ void embed_kernel(const int* __restrict__ nodef,
                             const int* __restrict__ typef,
                             const int* __restrict__ lenf,
                             const int* __restrict__ lanef,
                             const float* __restrict__ node_emb,
                             const float* __restrict__ type_emb,
                             const float* __restrict__ len_emb,
                             const float* __restrict__ lane_emb) {
    int u = blockIdx.x * blockDim.x + threadIdx.x;
    if (u >= N_NODES * 32) return;
    int n = u >> 5;
    int c = u & 31;
    float4 v;
    if (c < 4) {
        int f = lanef[n];
        v = reinterpret_cast<const float4*>(lane_emb + (size_t)f * 16)[c];
    } else if (c < 12) {
        int f = typef[n];
        v = reinterpret_cast<const float4*>(type_emb + (size_t)f * 32)[c - 4];
    } else if (c < 16) {
        int f = lenf[n];
        v = reinterpret_cast<const float4*>(len_emb + (size_t)f * 16)[c - 12];
    } else {
        int f = nodef[n];
        v = reinterpret_cast<const float4*>(node_emb + (size_t)f * 64)[c - 16];
    }
    reinterpret_cast<float4*>(g_A)[u] = v;
}

// ---------------- W fragment prep ----------------
// B of mma is the 8(k)x8(n) block of W; col-major fragment:
//   b0: k = lane&3,     n = lane>>2
//   b1: k = (lane&3)+4, n = lane>>2
// Buffer index: ((chunk*16 + ntile)*32 + lane)*2 + j  (j selects b0/b1)
__global__ void wfrag_kernel(const float* __restrict__ W) {
    int idx = blockIdx.x * blockDim.x + threadIdx.x;
    if (idx >= 16 * 16 * 32 * 2) return;
    int j    = idx & 1;
    int lane = (idx >> 1) & 31;
    int nt   = (idx >> 6) & 15;
    int c    = idx >> 10;
    int k = c * 8 + (lane & 3) + 4 * j;
    int n = nt * 8 + (lane >> 2);
    float w = W[k * 128 + n];
    uint32_t hi = tf32_rna(w);
    float lo = w - __uint_as_float(hi);
    g_Bfh[idx] = hi;
    g_Bfl[idx] = tf32_rna(lo);
}

// ---------------- GEMM: legacy mma.sync TF32, 3xTF32 split ----------------
// S[r][c] = sum_k X[r][k] * W[k][c].  CTA tile 128x128, 256 threads (8 warps).
// Warp (mw 0..3, nw 0..1): rows mw*32 + mt*16 (mt<2), cols nw*64 + nt*8 (nt<8).
#define AS_STRIDE 132
#define SM_AS_BYTES (128 * AS_STRIDE * 4)           // 67584
#define SM_BFH SM_AS_BYTES                           // +65536
#define SM_BFL (SM_AS_BYTES + 65536)                 // +65536
#define SMEM_GEMM (SM_AS_BYTES + 2 * 65536)          // 198656

__global__ __launch_bounds__(256)
void gemm_mma_kernel(const float* __restrict__ X,
                     float* __restrict__ S) {
    extern __shared__ char smem[];
    float*    As   = reinterpret_cast<float*>(smem);
    uint32_t* Bfhs = reinterpret_cast<uint32_t*>(smem + SM_BFH);
    uint32_t* Bfls = reinterpret_cast<uint32_t*>(smem + SM_BFL);
    int tid = threadIdx.x;
    int row0 = blockIdx.x * 128;

    // fill A tile (128x128 fp32, padded stride 132; float4 aligned since 132*4=528=33*16)
    for (int i = tid; i < 128 * 32; i += 256) {
        int r = i >> 5, c4 = i & 31;
        int gr = row0 + r;
        float4 v = make_float4(0.f, 0.f, 0.f, 0.f);
        if (gr < N_NODES)
            v = reinterpret_cast<const float4*>(X + (size_t)gr * 128)[c4];
        *reinterpret_cast<float4*>(As + r * AS_STRIDE + 4 * c4) = v;
    }
    // copy W fragments (hi+lo, 64KB each) flat
    for (int i = tid; i < 4096; i += 256) {
        reinterpret_cast<uint4*>(Bfhs)[i] = reinterpret_cast<const uint4*>(g_Bfh)[i];
        reinterpret_cast<uint4*>(Bfls)[i] = reinterpret_cast<const uint4*>(g_Bfl)[i];
    }
    __syncthreads();

    int lane = tid & 31, w = tid >> 5;
    int mw = w & 3, nw = w >> 2;
    int g = lane >> 2, t = lane & 3;

    float acc[2][8][4];
#pragma unroll
    for (int mt = 0; mt < 2; mt++)
#pragma unroll
        for (int nt = 0; nt < 8; nt++)
#pragma unroll
            for (int q = 0; q < 4; q++) acc[mt][nt][q] = 0.f;

    const float* Aw = As + (mw * 32) * AS_STRIDE;
    const uint2* Bh2 = reinterpret_cast<const uint2*>(Bfhs);
    const uint2* Bl2 = reinterpret_cast<const uint2*>(Bfls);

#pragma unroll 1
    for (int cc = 0; cc < 16; cc++) {
        int k0 = cc * 8;
        // A fragments (fp32 -> tf32 hi/lo in regs)
        uint32_t ah[2][4], al[2][4];
#pragma unroll
        for (int mt = 0; mt < 2; mt++) {
            int rb = mt * 16 + g;
            float f0 = Aw[rb * AS_STRIDE + k0 + t];
            float f1 = Aw[(rb + 8) * AS_STRIDE + k0 + t];
            float f2 = Aw[rb * AS_STRIDE + k0 + t + 4];
            float f3 = Aw[(rb + 8) * AS_STRIDE + k0 + t + 4];
            ah[mt][0] = tf32_rna(f0); al[mt][0] = tf32_rna(f0 - __uint_as_float(ah[mt][0]));
            ah[mt][1] = tf32_rna(f1); al[mt][1] = tf32_rna(f1 - __uint_as_float(ah[mt][1]));
            ah[mt][2] = tf32_rna(f2); al[mt][2] = tf32_rna(f2 - __uint_as_float(ah[mt][2]));
            ah[mt][3] = tf32_rna(f3); al[mt][3] = tf32_rna(f3 - __uint_as_float(ah[mt][3]));
        }
        int bbase = (cc * 16 + nw * 8) * 32 + lane;
#pragma unroll
        for (int nt = 0; nt < 8; nt++) {
            uint2 bh = Bh2[bbase + nt * 32];
            uint2 bl = Bl2[bbase + nt * 32];
#pragma unroll
            for (int mt = 0; mt < 2; mt++) {
                MMA_TF32(acc[mt][nt], ah[mt], bh.x, bh.y);   // Ah*Bh
                MMA_TF32(acc[mt][nt], al[mt], bh.x, bh.y);   // Al*Bh
                MMA_TF32(acc[mt][nt], ah[mt], bl.x, bl.y);   // Ah*Bl
            }
        }
    }

    // epilogue: D frag -> S.  c0/c1 at (row=g, col=2t,2t+1); c2/c3 at row g+8.
#pragma unroll
    for (int mt = 0; mt < 2; mt++) {
#pragma unroll
        for (int nt = 0; nt < 8; nt++) {
            int gr = row0 + mw * 32 + mt * 16 + g;
            int col = nw * 64 + nt * 8 + 2 * t;
            if (gr < N_NODES) {
                float2 v01 = make_float2(acc[mt][nt][0], acc[mt][nt][1]);
                *reinterpret_cast<float2*>(S + (size_t)gr * 128 + col) = v01;
            }
            if (gr + 8 < N_NODES) {
                float2 v23 = make_float2(acc[mt][nt][2], acc[mt][nt][3]);
                *reinterpret_cast<float2*>(S + (size_t)(gr + 8) * 128 + col) = v23;
            }
        }
    }
}

// ---------------- aggregation: out[d] = b + sum_{e: dst=d} val_e * S[src_e] ----------------
__global__ void agg_kernel(const float* __restrict__ S,
                           const float* __restrict__ b,
                           float* __restrict__ out) {
    int warp = (blockIdx.x * blockDim.x + threadIdx.x) >> 5;
    int lane = threadIdx.x & 31;
    if (warp >= N_NODES) return;
    float4 acc = reinterpret_cast<const float4*>(b)[lane];
    int s = g_rowptr[warp];
    int e = g_cursor[warp];
    for (int j = s; j < e; j++) {
        int src = __ldg(&g_csr_src[j]);
        float v = __ldg(&g_csr_val[j]);
        float4 x = reinterpret_cast<const float4*>(S + (size_t)src * 128)[lane];
        acc.x = fmaf(v, x.x, acc.x);
        acc.y = fmaf(v, x.y, acc.y);
        acc.z = fmaf(v, x.z, acc.z);
        acc.w = fmaf(v, x.w, acc.w);
    }
    reinterpret_cast<float4*>(out + (size_t)warp * 128)[lane] = acc;
}

// ---------------- launch ----------------
extern "C" void kernel_launch(void* const* d_in, const int* in_sizes, int n_in,
                              void* d_out, int out_size) {
    const int*   nodef    = (const int*)d_in[0];
    const int*   typef    = (const int*)d_in[1];
    const int*   lenf     = (const int*)d_in[2];
    const int*   lanef    = (const int*)d_in[3];
    const int*   adj_src  = (const int*)d_in[4];
    const int*   adj_dst  = (const int*)d_in[5];
    const float* adj_val  = (const float*)d_in[6];
    const float* node_emb = (const float*)d_in[7];
    const float* type_emb = (const float*)d_in[8];
    const float* len_emb  = (const float*)d_in[9];
    const float* lane_emb = (const float*)d_in[10];
    const float* W        = (const float*)d_in[11];
    const float* b        = (const float*)d_in[12];
    float* out = (float*)d_out;

    float *pA, *pB, *pS;
    int* pcnt;
    cudaGetSymbolAddress((void**)&pA, g_A);
    cudaGetSymbolAddress((void**)&pB, g_B);
    cudaGetSymbolAddress((void**)&pS, g_S);
    cudaGetSymbolAddress((void**)&pcnt, g_cnt);

    cudaFuncSetAttribute(gemm_mma_kernel, cudaFuncAttributeMaxDynamicSharedMemorySize, SMEM_GEMM);

    // ---- W fragment prep (hi/lo tf32, fragment order; reused by all 3 layers) ----
    wfrag_kernel<<<(16 * 16 * 32 * 2 + 255) / 256, 256>>>(W);

    // ---- CSR build (once per launch; reused by all 3 layers) ----
    cudaMemsetAsync(pcnt, 0, N_NODES * sizeof(int));
    hist_kernel<<<(N_EDGES + 255) / 256, 256>>>(adj_dst);
    const int nscan = (N_NODES + 1023) / 1024;
    scan1_kernel<<<nscan, 1024>>>();
    scan2_kernel<<<1, 32>>>(nscan);
    scan3_kernel<<<nscan, 1024>>>();
    scatter_kernel<<<(N_EDGES + 255) / 256, 256>>>(adj_src, adj_dst, adj_val);

    // ---- embedding concat -> A ----
    embed_kernel<<<(N_NODES * 32 + 255) / 256, 256>>>(nodef, typef, lenf, lanef,
                                                      node_emb, type_emb, len_emb, lane_emb);

    // ---- 3 shared-weight SPGCN layers ----
    const int gemm_blocks = (N_NODES + 127) / 128;   // 782
    const int agg_blocks  = (N_NODES * 32 + 255) / 256;

    gemm_mma_kernel<<<gemm_blocks, 256, SMEM_GEMM>>>(pA, pS);
    agg_kernel<<<agg_blocks, 256>>>(pS, b, pB);
    gemm_mma_kernel<<<gemm_blocks, 256, SMEM_GEMM>>>(pB, pS);
    agg_kernel<<<agg_blocks, 256>>>(pS, b, pA);
    gemm_mma_kernel<<<gemm_blocks, 256, SMEM_GEMM>>>(pA, pS);
    agg_kernel<<<agg_blocks, 256>>>(pS, b, out);
}

// round 10
// speedup vs baseline: 1.6118x; 1.6118x over previous
#include <cuda_runtime.h>
#include <cstdint>

#define N_NODES 100000
#define N_EDGES 640000
#define HID     128

// ---------------- scratch (static device globals; no allocation) ----------------
__device__ float g_A[(size_t)N_NODES * HID];   // ping
__device__ float g_B[(size_t)N_NODES * HID];   // pong
__device__ float g_S[(size_t)N_NODES * HID];   // support = X @ W
__device__ int   g_cnt[N_NODES];
__device__ int   g_rowptr[N_NODES];
__device__ int   g_cursor[N_NODES];
__device__ int   g_csr_src[N_EDGES];
__device__ float g_csr_val[N_EDGES];
__device__ int   g_blocksums[128];

// ---------------- CSR build ----------------
__global__ void hist_kernel(const int* __restrict__ dst) {
    int e = blockIdx.x * blockDim.x + threadIdx.x;
    if (e < N_EDGES) atomicAdd(&g_cnt[dst[e]], 1);
}

__global__ void scan1_kernel() {
    __shared__ int sh[1024];
    int tid = threadIdx.x;
    int i = blockIdx.x * 1024 + tid;
    int v = (i < N_NODES) ? g_cnt[i] : 0;
    sh[tid] = v;
    __syncthreads();
    for (int off = 1; off < 1024; off <<= 1) {
        int t = (tid >= off) ? sh[tid - off] : 0;
        __syncthreads();
        sh[tid] += t;
        __syncthreads();
    }
    if (i < N_NODES) g_rowptr[i] = sh[tid] - v;   // exclusive
    if (tid == 1023) g_blocksums[blockIdx.x] = sh[1023];
}

// parallel exclusive scan of the <=128 block sums
__global__ void scan2_kernel(int nblocks) {
    __shared__ int sh[128];
    int tid = threadIdx.x;
    int v = (tid < nblocks) ? g_blocksums[tid] : 0;
    sh[tid] = v;
    __syncthreads();
    for (int off = 1; off < 128; off <<= 1) {
        int t = (tid >= off) ? sh[tid - off] : 0;
        __syncthreads();
        sh[tid] += t;
        __syncthreads();
    }
    if (tid < nblocks) g_blocksums[tid] = sh[tid] - v;   // exclusive
}

__global__ void scan3_kernel() {
    int i = blockIdx.x * 1024 + threadIdx.x;
    if (i < N_NODES) {
        int r = g_rowptr[i] + g_blocksums[blockIdx.x];
        g_rowptr[i] = r;
        g_cursor[i] = r;
    }
}

__global__ void scatter_kernel(const int* __restrict__ src,
                               const int* __restrict__ dst,
                               const float* __restrict__ val) {
    int e = blockIdx.x * blockDim.x + threadIdx.x;
    if (e < N_EDGES) {
        int d = dst[e];
        int pos = atomicAdd(&g_cursor[d], 1);
        g_csr_src[pos] = src[e];
        g_csr_val[pos] = val[e];
    }
}

// ---------------- embedding concat ----------------
__global__ void embed_kernel(const int* __restrict__ nodef,
                             const int* __restrict__ typef,
                             const int* __restrict__ lenf,
                             const int* __restrict__ lanef,
                             const float* __restrict__ node_emb,
                             const float* __restrict__ type_emb,
                             const float* __restrict__ len_emb,
                             const float* __restrict__ lane_emb) {
    int u = blockIdx.x * blockDim.x + threadIdx.x;
    if (u >= N_NODES * 32) return;
    int n = u >> 5;
    int c = u & 31;
    float4 v;
    if (c < 4) {
        int f = lanef[n];
        v = reinterpret_cast<const float4*>(lane_emb + (size_t)f * 16)[c];
    } else if (c < 12) {
        int f = typef[n];
        v = reinterpret_cast<const float4*>(type_emb + (size_t)f * 32)[c - 4];
    } else if (c < 16) {
        int f = lenf[n];
        v = reinterpret_cast<const float4*>(len_emb + (size_t)f * 16)[c - 12];
    } else {
        int f = nodef[n];
        v = reinterpret_cast<const float4*>(node_emb + (size_t)f * 64)[c - 16];
    }
    reinterpret_cast<float4*>(g_A)[u] = v;
}

// ---------------- GEMM via packed f32x2 FFMA2, persistent CTAs, 2 CTAs/SM ----------------
// S[r][c] = sum_k X[r][k] * W[k][c].  Tile: 64 rows x 128 cols.  256 threads.
// Thread (ty=tid>>4, tx=tid&15): rows ty*4+i (i<4), col-pairs (2tx+32j, 2tx+32j+1) j<4.
// W (64KB) loaded ONCE per CTA; loop over tiles grid-stride.
// XS_STRIDE=132: row pitch 528 B = 33*16 -> float4 stores aligned; broadcast reads
// for the two ty values in a warp land in different banks (2112 B apart -> bank+16).
#define XS_STRIDE 132
#define GEMM_TILES ((N_NODES + 63) / 64)      // 1563
#define SMEM_GEMM ((128 * 128 + 64 * XS_STRIDE) * 4)   // 99328 B

__device__ __forceinline__ void ffma2(unsigned long long& acc,
                                      unsigned long long a,
                                      unsigned long long b) {
    asm("fma.rn.f32x2 %0, %1, %2, %0;" : "+l"(acc) : "l"(a), "l"(b));
}

__global__ __launch_bounds__(256, 2)
void gemm_kernel(const float* __restrict__ X,
                 const float* __restrict__ W,
                 float* __restrict__ S) {
    extern __shared__ float sh[];
    float* ws = sh;                       // 128*128
    float* xs = sh + 128 * 128;           // 64 * XS_STRIDE
    int tid = threadIdx.x;

    // load W once (coalesced float4)
    for (int i = tid; i < 128 * 128 / 4; i += 256)
        reinterpret_cast<float4*>(ws)[i] = reinterpret_cast<const float4*>(W)[i];

    int tx = tid & 15;
    int ty = tid >> 4;
    const float* wcol = ws + 2 * tx;

    for (int tile = blockIdx.x; tile < GEMM_TILES; tile += gridDim.x) {
        int row0 = tile * 64;
        __syncthreads();   // xs free (previous compute done / W loaded)
        // load X tile (64 x 128) into padded xs (aligned float4 stores)
        for (int i = tid; i < 64 * 32; i += 256) {
            int r = i >> 5, c4 = i & 31;
            int gr = row0 + r;
            float4 v = make_float4(0.f, 0.f, 0.f, 0.f);
            if (gr < N_NODES)
                v = reinterpret_cast<const float4*>(X + (size_t)gr * 128)[c4];
            *reinterpret_cast<float4*>(xs + r * XS_STRIDE + 4 * c4) = v;
        }
        __syncthreads();

        const float* xrow = xs + ty * 4 * XS_STRIDE;
        unsigned long long acc[4][4];
#pragma unroll
        for (int i = 0; i < 4; i++)
#pragma unroll
            for (int j = 0; j < 4; j++) acc[i][j] = 0ull;

#pragma unroll 4
        for (int k = 0; k < 128; k++) {
            unsigned long long wv[4];
#pragma unroll
            for (int j = 0; j < 4; j++)
                wv[j] = *reinterpret_cast<const unsigned long long*>(wcol + k * 128 + 32 * j);
            unsigned long long xb[4];
#pragma unroll
            for (int i = 0; i < 4; i++) {
                float xv = xrow[i * XS_STRIDE + k];
                asm("mov.b64 %0, {%1, %1};" : "=l"(xb[i]) : "f"(xv));
            }
#pragma unroll
            for (int i = 0; i < 4; i++)
#pragma unroll
                for (int j = 0; j < 4; j++)
                    ffma2(acc[i][j], xb[i], wv[j]);
        }

        // epilogue: float2 stores, coalesced
#pragma unroll
        for (int i = 0; i < 4; i++) {
            int gr = row0 + ty * 4 + i;
            if (gr < N_NODES) {
                float* out = S + (size_t)gr * 128 + 2 * tx;
#pragma unroll
                for (int j = 0; j < 4; j++)
                    *reinterpret_cast<float2*>(out + 32 * j) =
                        *reinterpret_cast<float2*>(&acc[i][j]);
            }
        }
    }
}

// ---------------- aggregation: out[d] = b + sum_{e: dst=d} val_e * S[src_e] ----------------
__global__ void agg_kernel(const float* __restrict__ S,
                           const float* __restrict__ b,
                           float* __restrict__ out) {
    int warp = (blockIdx.x * blockDim.x + threadIdx.x) >> 5;
    int lane = threadIdx.x & 31;
    if (warp >= N_NODES) return;
    float4 acc = reinterpret_cast<const float4*>(b)[lane];
    int s = g_rowptr[warp];
    int e = g_cursor[warp];
    for (int j = s; j < e; j++) {
        int src = __ldg(&g_csr_src[j]);
        float v = __ldg(&g_csr_val[j]);
        float4 x = reinterpret_cast<const float4*>(S + (size_t)src * 128)[lane];
        acc.x = fmaf(v, x.x, acc.x);
        acc.y = fmaf(v, x.y, acc.y);
        acc.z = fmaf(v, x.z, acc.z);
        acc.w = fmaf(v, x.w, acc.w);
    }
    reinterpret_cast<float4*>(out + (size_t)warp * 128)[lane] = acc;
}

// ---------------- launch ----------------
extern "C" void kernel_launch(void* const* d_in, const int* in_sizes, int n_in,
                              void* d_out, int out_size) {
    const int*   nodef    = (const int*)d_in[0];
    const int*   typef    = (const int*)d_in[1];
    const int*   lenf     = (const int*)d_in[2];
    const int*   lanef    = (const int*)d_in[3];
    const int*   adj_src  = (const int*)d_in[4];
    const int*   adj_dst  = (const int*)d_in[5];
    const float* adj_val  = (const float*)d_in[6];
    const float* node_emb = (const float*)d_in[7];
    const float* type_emb = (const float*)d_in[8];
    const float* len_emb  = (const float*)d_in[9];
    const float* lane_emb = (const float*)d_in[10];
    const float* W        = (const float*)d_in[11];
    const float* b        = (const float*)d_in[12];
    float* out = (float*)d_out;

    float *pA, *pB, *pS;
    int* pcnt;
    cudaGetSymbolAddress((void**)&pA, g_A);
    cudaGetSymbolAddress((void**)&pB, g_B);
    cudaGetSymbolAddress((void**)&pS, g_S);
    cudaGetSymbolAddress((void**)&pcnt, g_cnt);

    cudaFuncSetAttribute(gemm_kernel, cudaFuncAttributeMaxDynamicSharedMemorySize, SMEM_GEMM);

    // ---- CSR build (once per launch; reused by all 3 layers) ----
    cudaMemsetAsync(pcnt, 0, N_NODES * sizeof(int));
    hist_kernel<<<(N_EDGES + 255) / 256, 256>>>(adj_dst);
    const int nscan = (N_NODES + 1023) / 1024;          // 98
    scan1_kernel<<<nscan, 1024>>>();
    scan2_kernel<<<1, 128>>>(nscan);
    scan3_kernel<<<nscan, 1024>>>();
    scatter_kernel<<<(N_EDGES + 255) / 256, 256>>>(adj_src, adj_dst, adj_val);

    // ---- embedding concat -> A ----
    embed_kernel<<<(N_NODES * 32 + 255) / 256, 256>>>(nodef, typef, lenf, lanef,
                                                      node_emb, type_emb, len_emb, lane_emb);

    // ---- 3 shared-weight SPGCN layers ----
    const int gemm_blocks = 2 * 148;                    // persistent, 2 CTAs/SM
    const int agg_blocks  = (N_NODES * 32 + 255) / 256;

    gemm_kernel<<<gemm_blocks, 256, SMEM_GEMM>>>(pA, W, pS);
    agg_kernel<<<agg_blocks, 256>>>(pS, b, pB);
    gemm_kernel<<<gemm_blocks, 256, SMEM_GEMM>>>(pB, W, pS);
    agg_kernel<<<agg_blocks, 256>>>(pS, b, pA);
    gemm_kernel<<<gemm_blocks, 256, SMEM_GEMM>>>(pA, W, pS);
    agg_kernel<<<agg_blocks, 256>>>(pS, b, out);
}